// round 16
// baseline (speedup 1.0000x reference)
#include <cuda_runtime.h>

typedef unsigned long long u64;

#define NH   10
#define NL   10
#define TPB  128
#define PPT  4

// ---- raw weight layout in cw (float offsets; all 8B-pair offsets even) ----
#define OFF_W0   0
#define OFF_B0   30
#define OFF_W1   40
#define OFF_B1   140
#define OFF_WR1  150
#define OFF_BR1  1150
#define OFF_WR2  1250
#define OFF_BR2  2250
#define OFF_WR3  2350
#define OFF_BR3  3350
#define OFF_W8   3450
#define OFF_B8   3550
#define OFF_W9   3560
#define OFF_B9   3570
#define CW_TOTAL 3572
#define OFF_B23  3572            // precomputed B2+B3, [10][10] raw floats
#define CW_EXT   3672

__constant__ __align__(16) float cw[CW_EXT];
__device__   float b23buf[100];

// ---- helpers ----
// non-duplicated weight PAIR (w_j, w_j+1): ONE warp-uniform 8B constant load (LDCU)
__device__ __forceinline__ u64 ldk(int i) {
    return *reinterpret_cast<const u64*>(&cw[i]);
}
// packed fp32x2 FMA: d = a*b + c, all operands b64 pairs
__device__ __forceinline__ u64 fma2(u64 a, u64 b, u64 c) {
    u64 d; asm("fma.rn.f32x2 %0, %1, %2, %3;" : "=l"(d) : "l"(a), "l"(b), "l"(c)); return d;
}
// duplicate a scalar into both b64 lanes via TWO alu-pipe integer adds of opaque zeros
__device__ __forceinline__ u64 dupa(float h, unsigned z1, unsigned z2) {
    unsigned ui = __float_as_uint(h);
    unsigned lo = ui + z1;
    unsigned hi = ui + z2;
    u64 r; asm("mov.b64 %0, {%1, %2};" : "=l"(r) : "r"(lo), "r"(hi)); return r;
}
// decompose pair into scalar halves (register aliasing; ~free)
__device__ __forceinline__ void up2(u64 v, float& lo, float& hi) {
    asm("mov.b64 {%0, %1}, %2;" : "=f"(lo), "=f"(hi) : "l"(v));
}
// fused relu+duplicate: from acc pair (a_j, a_j1) produce TWO dup pairs
//   o0 = (relu(a_j), relu(a_j)),  o1 = (relu(a_j1), relu(a_j1))
// via 4 independent FMNMX (alu pipe). z1/z2 are runtime 0.0f kernel args ->
// the two max's per half have distinct operands (no CSE into mov on fma pipe).
__device__ __forceinline__ void reludup2(u64 acc, float z1, float z2, u64& o0, u64& o1) {
    asm("{\n\t"
        ".reg .f32 lo, hi, r0, r1, r2, r3;\n\t"
        "mov.b64 {lo, hi}, %2;\n\t"
        "max.f32 r0, lo, %3;\n\t"
        "max.f32 r1, lo, %4;\n\t"
        "max.f32 r2, hi, %3;\n\t"
        "max.f32 r3, hi, %4;\n\t"
        "mov.b64 %0, {r0, r1};\n\t"
        "mov.b64 %1, {r2, r3};\n\t"
        "}" : "=l"(o0), "=l"(o1) : "l"(acc), "f"(z1), "f"(z2));
}

// dense + relu: h stored as dup pairs, acc j-pair packed, weights non-dup LDCU.
// Reads all of h before writing out -> in-place safe (out may alias h).
template<int K>
__device__ __forceinline__ void dense(int Wo, int Bo, float z1, float z2,
                                      const u64 (&h)[PPT][K], u64 (&out)[PPT][NH])
{
    u64 acc[PPT][NH/2];
#pragma unroll
    for (int j2 = 0; j2 < NH/2; j2++) {            // k=0: bias pair as FMA addend
        u64 b = ldk(Bo + 2*j2);
        u64 w = ldk(Wo + 2*j2);
#pragma unroll
        for (int p = 0; p < PPT; p++) acc[p][j2] = fma2(h[p][0], w, b);
    }
#pragma unroll
    for (int k = 1; k < K; k++) {
#pragma unroll
        for (int j2 = 0; j2 < NH/2; j2++) {
            u64 w = ldk(Wo + k*NH + 2*j2);
#pragma unroll
            for (int p = 0; p < PPT; p++) acc[p][j2] = fma2(h[p][k], w, acc[p][j2]);
        }
    }
#pragma unroll
    for (int p = 0; p < PPT; p++)
#pragma unroll
        for (int j2 = 0; j2 < NH/2; j2++)
            reludup2(acc[p][j2], z1, z2, out[p][2*j2], out[p][2*j2+1]);
}

// residual: out = relu( h1 @ W3 + h0 @ W2 + (B2+B3) ); in-place safe on h0
__device__ __forceinline__ void dense_res(int W3o, int W2o, int B23o, float z1, float z2,
                                          const u64 (&h1)[PPT][NH],
                                          const u64 (&h0)[PPT][NH],
                                          u64 (&out)[PPT][NH])
{
    u64 acc[PPT][NH/2];
#pragma unroll
    for (int j2 = 0; j2 < NH/2; j2++) {            // k=0 of W3, B23 as addend
        u64 b = ldk(B23o + 2*j2);
        u64 w = ldk(W3o + 2*j2);
#pragma unroll
        for (int p = 0; p < PPT; p++) acc[p][j2] = fma2(h1[p][0], w, b);
    }
#pragma unroll
    for (int k = 1; k < NH; k++) {
#pragma unroll
        for (int j2 = 0; j2 < NH/2; j2++) {
            u64 w = ldk(W3o + k*NH + 2*j2);
#pragma unroll
            for (int p = 0; p < PPT; p++) acc[p][j2] = fma2(h1[p][k], w, acc[p][j2]);
        }
    }
#pragma unroll
    for (int k = 0; k < NH; k++) {
#pragma unroll
        for (int j2 = 0; j2 < NH/2; j2++) {
            u64 w = ldk(W2o + k*NH + 2*j2);
#pragma unroll
            for (int p = 0; p < PPT; p++) acc[p][j2] = fma2(h0[p][k], w, acc[p][j2]);
        }
    }
#pragma unroll
    for (int p = 0; p < PPT; p++)
#pragma unroll
        for (int j2 = 0; j2 < NH/2; j2++)
            reludup2(acc[p][j2], z1, z2, out[p][2*j2], out[p][2*j2+1]);
}

__global__ void prep_kernel()
{
    for (int i = threadIdx.x; i < 100; i += blockDim.x)
        b23buf[i] = cw[OFF_BR2 + i] + cw[OFF_BR3 + i];
}

__global__ void __launch_bounds__(TPB, 4)
resnet_kernel(const float4* __restrict__ x4, float4* __restrict__ out4, int nthreads,
              float zf1, float zf2)
{
    int t = blockIdx.x * TPB + threadIdx.x;
    if (t >= nthreads) return;

    unsigned zu1 = __float_as_uint(zf1);
    unsigned zu2 = __float_as_uint(zf2);

    // 4 points = 12 contiguous floats = 3 aligned float4 loads
    float4 a = x4[3*t + 0];
    float4 b = x4[3*t + 1];
    float4 c = x4[3*t + 2];
    // inputs as dup pairs (alu-pipe dup; one-time, 24 IADD3)
    u64 xin[PPT][3] = {
        { dupa(a.x, zu1, zu2), dupa(a.y, zu1, zu2), dupa(a.z, zu1, zu2) },
        { dupa(a.w, zu1, zu2), dupa(b.x, zu1, zu2), dupa(b.y, zu1, zu2) },
        { dupa(b.z, zu1, zu2), dupa(b.w, zu1, zu2), dupa(c.x, zu1, zu2) },
        { dupa(c.y, zu1, zu2), dupa(c.z, zu1, zu2), dupa(c.w, zu1, zu2) }
    };

    u64 h [PPT][NH];
    u64 h1[PPT][NH];

    dense<3 >(OFF_W0, OFF_B0, zf1, zf2, xin, h);
    dense<NH>(OFF_W1, OFF_B1, zf1, zf2, h,   h);

#pragma unroll 1
    for (int l = 0; l < NL; l++) {
        dense<NH>(OFF_WR1 + l*100, OFF_BR1 + l*10, zf1, zf2, h, h1);
        dense_res(OFF_WR3 + l*100, OFF_WR2 + l*100, OFF_B23 + l*10, zf1, zf2, h1, h, h);
    }

    dense<NH>(OFF_W8, OFF_B8, zf1, zf2, h, h);

    // final [10]->[1]: scalar FFMA on the lo half of each dup pair
    float o[PPT];
    float b9 = cw[OFF_B9];
#pragma unroll
    for (int p = 0; p < PPT; p++) o[p] = b9;
#pragma unroll
    for (int k = 0; k < NH; k++) {
        float wk = cw[OFF_W9 + k];
#pragma unroll
        for (int p = 0; p < PPT; p++) {
            float lo, hi; up2(h[p][k], lo, hi);
            o[p] = fmaf(lo, wk, o[p]);
        }
    }
    out4[t] = make_float4(o[0], o[1], o[2], o[3]);
}

extern "C" void kernel_launch(void* const* d_in, const int* in_sizes, int n_in,
                              void* d_out, int out_size)
{
    // stage raw weights into constant memory (D2D async copies: graph-capturable)
    static const int idx[14] = {1, 2, 3, 4, 5, 6, 7, 8, 9, 10, 11, 12, 13, 14};
    static const int off[14] = {OFF_W0, OFF_B0, OFF_W1, OFF_B1,
                                OFF_WR1, OFF_BR1, OFF_WR2, OFF_BR2, OFF_WR3, OFF_BR3,
                                OFF_W8, OFF_B8, OFF_W9, OFF_B9};
    static const int cnt[14] = {30, 10, 100, 10, 1000, 100, 1000, 100, 1000, 100, 100, 10, 10, 1};
    for (int i = 0; i < 14; i++) {
        cudaMemcpyToSymbolAsync(cw, d_in[idx[i]], (size_t)cnt[i] * sizeof(float),
                                (size_t)off[i] * sizeof(float),
                                cudaMemcpyDeviceToDevice, 0);
    }

    // compute B2+B3 on device, then append into the constant table
    prep_kernel<<<1, 128>>>();
    void* b23_ptr = nullptr;
    cudaGetSymbolAddress(&b23_ptr, b23buf);
    cudaMemcpyToSymbolAsync(cw, b23_ptr, 100 * sizeof(float),
                            (size_t)OFF_B23 * sizeof(float),
                            cudaMemcpyDeviceToDevice, 0);

    int npts     = in_sizes[0] / 3;   // x is [N,3]
    int nthreads = npts / PPT;        // 4 points per thread
    int nblocks  = (nthreads + TPB - 1) / TPB;
    resnet_kernel<<<nblocks, TPB>>>((const float4*)d_in[0], (float4*)d_out, nthreads,
                                    0.0f, 0.0f);
}

// round 17
// speedup vs baseline: 1.6908x; 1.6908x over previous
#include <cuda_runtime.h>

typedef unsigned long long u64;

#define NH   10
#define NL   10
#define TPB  128
#define PPT  4

// ---- raw weight layout in cw (float offsets; all 8B-pair offsets even) ----
#define OFF_W0   0
#define OFF_B0   30
#define OFF_W1   40
#define OFF_B1   140
#define OFF_WR1  150
#define OFF_BR1  1150
#define OFF_WR2  1250
#define OFF_BR2  2250
#define OFF_WR3  2350
#define OFF_BR3  3350
#define OFF_W8   3450
#define OFF_B8   3550
#define OFF_W9   3560
#define OFF_B9   3570
#define CW_TOTAL 3572
#define OFF_B23  3572            // precomputed B2+B3, [10][10] raw floats
#define CW_EXT   3672

__constant__ __align__(16) float cw[CW_EXT];
__device__   float b23buf[100];

// ---- helpers ----
// non-duplicated weight PAIR (w_j, w_j+1): ONE warp-uniform 8B constant load (LDCU)
__device__ __forceinline__ u64 ldk(int i) {
    return *reinterpret_cast<const u64*>(&cw[i]);
}
// packed fp32x2 FMA: d = a*b + c, all operands b64 pairs
__device__ __forceinline__ u64 fma2(u64 a, u64 b, u64 c) {
    u64 d; asm("fma.rn.f32x2 %0, %1, %2, %3;" : "=l"(d) : "l"(a), "l"(b), "l"(c)); return d;
}
// duplicate a scalar into a b64 pair with ONE alu-pipe add:
//   pair = (h + opaque_zero, h)
// The hi half reuses h's own register (allocator coalesces the compose);
// only the lo half needs a real IADD3 (z1 is a runtime-0 kernel arg, not foldable).
__device__ __forceinline__ u64 dupa(float h, unsigned z1) {
    unsigned ui = __float_as_uint(h);       // reinterpret, no instruction
    unsigned lo = ui + z1;                  // IADD3 (alu pipe)
    u64 r; asm("mov.b64 %0, {%1, %2};" : "=l"(r) : "r"(lo), "r"(ui)); return r;
}
// decompose pair into scalar halves (register aliasing; ~free)
__device__ __forceinline__ void up2(u64 v, float& lo, float& hi) {
    asm("mov.b64 {%0, %1}, %2;" : "=f"(lo), "=f"(hi) : "l"(v));
}

// dense + relu: out[p][j] = relu( sum_k h[p][k] * W[k][j] + B[j] )
// j-pair-packed accumulators, scalar h in/out. Reads all h before writing -> in-place safe.
template<int K>
__device__ __forceinline__ void dense(int Wo, int Bo, unsigned z1,
                                      const float (&h)[PPT][K], float (&out)[PPT][NH])
{
    u64 acc[PPT][NH/2];
    {   // k = 0: bias pair folded as the FMA addend
        u64 hd[PPT];
#pragma unroll
        for (int p = 0; p < PPT; p++) hd[p] = dupa(h[p][0], z1);
#pragma unroll
        for (int j2 = 0; j2 < NH/2; j2++) {
            u64 b = ldk(Bo + 2*j2);
            u64 w = ldk(Wo + 2*j2);
#pragma unroll
            for (int p = 0; p < PPT; p++) acc[p][j2] = fma2(hd[p], w, b);
        }
    }
#pragma unroll
    for (int k = 1; k < K; k++) {
        u64 hd[PPT];
#pragma unroll
        for (int p = 0; p < PPT; p++) hd[p] = dupa(h[p][k], z1);
#pragma unroll
        for (int j2 = 0; j2 < NH/2; j2++) {
            u64 w = ldk(Wo + k*NH + 2*j2);
#pragma unroll
            for (int p = 0; p < PPT; p++) acc[p][j2] = fma2(hd[p], w, acc[p][j2]);
        }
    }
#pragma unroll
    for (int p = 0; p < PPT; p++)
#pragma unroll
        for (int j2 = 0; j2 < NH/2; j2++) {
            float lo, hi; up2(acc[p][j2], lo, hi);
            out[p][2*j2]   = fmaxf(lo, 0.0f);   // FMNMX -> alu pipe
            out[p][2*j2+1] = fmaxf(hi, 0.0f);
        }
}

// residual: out = relu( h1 @ W3 + h0 @ W2 + (B2+B3) ); in-place safe on h0
__device__ __forceinline__ void dense_res(int W3o, int W2o, int B23o, unsigned z1,
                                          const float (&h1)[PPT][NH],
                                          const float (&h0)[PPT][NH],
                                          float (&out)[PPT][NH])
{
    u64 acc[PPT][NH/2];
    {   // k = 0 of W3, B23 as addend
        u64 hd[PPT];
#pragma unroll
        for (int p = 0; p < PPT; p++) hd[p] = dupa(h1[p][0], z1);
#pragma unroll
        for (int j2 = 0; j2 < NH/2; j2++) {
            u64 b = ldk(B23o + 2*j2);
            u64 w = ldk(W3o + 2*j2);
#pragma unroll
            for (int p = 0; p < PPT; p++) acc[p][j2] = fma2(hd[p], w, b);
        }
    }
#pragma unroll
    for (int k = 1; k < NH; k++) {
        u64 hd[PPT];
#pragma unroll
        for (int p = 0; p < PPT; p++) hd[p] = dupa(h1[p][k], z1);
#pragma unroll
        for (int j2 = 0; j2 < NH/2; j2++) {
            u64 w = ldk(W3o + k*NH + 2*j2);
#pragma unroll
            for (int p = 0; p < PPT; p++) acc[p][j2] = fma2(hd[p], w, acc[p][j2]);
        }
    }
#pragma unroll
    for (int k = 0; k < NH; k++) {
        u64 hd[PPT];
#pragma unroll
        for (int p = 0; p < PPT; p++) hd[p] = dupa(h0[p][k], z1);
#pragma unroll
        for (int j2 = 0; j2 < NH/2; j2++) {
            u64 w = ldk(W2o + k*NH + 2*j2);
#pragma unroll
            for (int p = 0; p < PPT; p++) acc[p][j2] = fma2(hd[p], w, acc[p][j2]);
        }
    }
#pragma unroll
    for (int p = 0; p < PPT; p++)
#pragma unroll
        for (int j2 = 0; j2 < NH/2; j2++) {
            float lo, hi; up2(acc[p][j2], lo, hi);
            out[p][2*j2]   = fmaxf(lo, 0.0f);
            out[p][2*j2+1] = fmaxf(hi, 0.0f);
        }
}

__global__ void prep_kernel()
{
    for (int i = threadIdx.x; i < 100; i += blockDim.x)
        b23buf[i] = cw[OFF_BR2 + i] + cw[OFF_BR3 + i];
}

__global__ void __launch_bounds__(TPB, 4)
resnet_kernel(const float4* __restrict__ x4, float4* __restrict__ out4, int nthreads,
              unsigned z1)
{
    int t = blockIdx.x * TPB + threadIdx.x;
    if (t >= nthreads) return;

    // 4 points = 12 contiguous floats = 3 aligned float4 loads
    float4 a = x4[3*t + 0];
    float4 b = x4[3*t + 1];
    float4 c = x4[3*t + 2];
    float xin[PPT][3] = {
        {a.x, a.y, a.z},
        {a.w, b.x, b.y},
        {b.z, b.w, c.x},
        {c.y, c.z, c.w}
    };

    float h [PPT][NH];
    float h1[PPT][NH];

    dense<3 >(OFF_W0, OFF_B0, z1, xin, h);
    dense<NH>(OFF_W1, OFF_B1, z1, h,   h);

#pragma unroll 1
    for (int l = 0; l < NL; l++) {
        dense<NH>(OFF_WR1 + l*100, OFF_BR1 + l*10, z1, h, h1);
        dense_res(OFF_WR3 + l*100, OFF_WR2 + l*100, OFF_B23 + l*10, z1, h1, h, h);
    }

    dense<NH>(OFF_W8, OFF_B8, z1, h, h);

    // final [10]->[1], scalar FFMA
    float o[PPT];
    float b9 = cw[OFF_B9];
#pragma unroll
    for (int p = 0; p < PPT; p++) o[p] = b9;
#pragma unroll
    for (int k = 0; k < NH; k++) {
        float wk = cw[OFF_W9 + k];
#pragma unroll
        for (int p = 0; p < PPT; p++) o[p] = fmaf(h[p][k], wk, o[p]);
    }
    out4[t] = make_float4(o[0], o[1], o[2], o[3]);
}

extern "C" void kernel_launch(void* const* d_in, const int* in_sizes, int n_in,
                              void* d_out, int out_size)
{
    // stage raw weights into constant memory (D2D async copies: graph-capturable)
    static const int idx[14] = {1, 2, 3, 4, 5, 6, 7, 8, 9, 10, 11, 12, 13, 14};
    static const int off[14] = {OFF_W0, OFF_B0, OFF_W1, OFF_B1,
                                OFF_WR1, OFF_BR1, OFF_WR2, OFF_BR2, OFF_WR3, OFF_BR3,
                                OFF_W8, OFF_B8, OFF_W9, OFF_B9};
    static const int cnt[14] = {30, 10, 100, 10, 1000, 100, 1000, 100, 1000, 100, 100, 10, 10, 1};
    for (int i = 0; i < 14; i++) {
        cudaMemcpyToSymbolAsync(cw, d_in[idx[i]], (size_t)cnt[i] * sizeof(float),
                                (size_t)off[i] * sizeof(float),
                                cudaMemcpyDeviceToDevice, 0);
    }

    // compute B2+B3 on device, then append into the constant table
    prep_kernel<<<1, 128>>>();
    void* b23_ptr = nullptr;
    cudaGetSymbolAddress(&b23_ptr, b23buf);
    cudaMemcpyToSymbolAsync(cw, b23_ptr, 100 * sizeof(float),
                            (size_t)OFF_B23 * sizeof(float),
                            cudaMemcpyDeviceToDevice, 0);

    int npts     = in_sizes[0] / 3;   // x is [N,3]
    int nthreads = npts / PPT;        // 4 points per thread
    int nblocks  = (nthreads + TPB - 1) / TPB;
    resnet_kernel<<<nblocks, TPB>>>((const float4*)d_in[0], (float4*)d_out, nthreads,
                                    0u);
}